// round 6
// baseline (speedup 1.0000x reference)
#include <cuda_runtime.h>
#include <cuda_bf16.h>

// Problem constants
#define ZB 8
#define ZC 128
#define ZW 64
#define ZH 64
#define LDIM 16
#define KCODES 256
#define CDIM 8
#define NPOS (ZB * ZW * ZH)   // 32768 spatial positions
#define WHPLANE (ZW * ZH)     // 4096

typedef unsigned long long u64;

// log2(e)^2 and -2*log2(e)^2 ; 1/S2n to un-scale the soft accumulator
#define S1 2.0813689810056077f
#define S2n (-4.1627379620112154f)
#define INV_S2n (-0.24022650695910071f)

// ---- packed f32x2 helpers (sm_103a) ----
__device__ __forceinline__ u64 pk2(float lo, float hi) {
    u64 r; asm("mov.b64 %0, {%1, %2};" : "=l"(r) : "f"(lo), "f"(hi)); return r;
}
__device__ __forceinline__ void upk2(u64 p, float& lo, float& hi) {
    asm("mov.b64 {%0, %1}, %2;" : "=f"(lo), "=f"(hi) : "l"(p));
}
__device__ __forceinline__ u64 ffma2(u64 a, u64 b, u64 c) {
    u64 d; asm("fma.rn.f32x2 %0, %1, %2, %3;" : "=l"(d) : "l"(a), "l"(b), "l"(c)); return d;
}
__device__ __forceinline__ u64 fmul2(u64 a, u64 b) {
    u64 d; asm("mul.rn.f32x2 %0, %1, %2;" : "=l"(d) : "l"(a), "l"(b)); return d;
}
__device__ __forceinline__ u64 fadd2(u64 a, u64 b) {
    u64 d; asm("add.rn.f32x2 %0, %1, %2;" : "=l"(d) : "l"(a), "l"(b)); return d;
}
__device__ __forceinline__ float sqrt_ap(float x) {
    float r; asm("sqrt.approx.f32 %0, %1;" : "=f"(r) : "f"(x)); return r;
}
__device__ __forceinline__ float ex2_ap(float x) {
    float r; asm("ex2.approx.f32 %0, %1;" : "=f"(r) : "f"(x)); return r;
}

// One block = one latent l (blockIdx.y) x 256 positions (blockIdx.x).
// Each thread owns one (pos, l): loops over K=256 codes in PAIRS.
// f32x2 lanes = (code 2j, code 2j+1) of the same channel. The dot work is
// split into two independent half-chains (shorter critical path), norms are
// pre-packed, argmin uses FMNMX + one select.
__global__ void __launch_bounds__(256, 4)
sth_kernel(const float* __restrict__ z, const float* __restrict__ codes,
           float* __restrict__ out_soft, float* __restrict__ out_hard,
           float* __restrict__ out_idx)
{
    const int l   = blockIdx.y;
    const int tid = threadIdx.x;
    const int pos = blockIdx.x * 256 + tid;

    // Transposed, pre-scaled codebook: sct[j][i] = (S2n*c_{2j}[i], S2n*c_{2j+1}[i])
    __shared__ u64 sct[KCODES / 2][CDIM];  // 8 KB
    __shared__ u64 ssn[KCODES / 2];        // (S1*||c_2j||^2, S1*||c_2j+1||^2) 1 KB

    // Cooperative codebook load: one code per thread (256 threads == 256 codes)
    {
        const float4* cl = reinterpret_cast<const float4*>(codes)
                         + (size_t)l * (KCODES * 2) + 2 * tid;
        const float4 a = cl[0];
        const float4 b = cl[1];
        float* sf = reinterpret_cast<float*>(sct);
        const int j = tid >> 1, lane = tid & 1;
        const int base = j * (CDIM * 2) + lane;
        sf[base +  0] = S2n * a.x;
        sf[base +  2] = S2n * a.y;
        sf[base +  4] = S2n * a.z;
        sf[base +  6] = S2n * a.w;
        sf[base +  8] = S2n * b.x;
        sf[base + 10] = S2n * b.y;
        sf[base + 12] = S2n * b.z;
        sf[base + 14] = S2n * b.w;
        reinterpret_cast<float*>(ssn)[tid] =
            S1 * (a.x * a.x + a.y * a.y + a.z * a.z + a.w * a.w
                + b.x * b.x + b.y * b.y + b.z * b.z + b.w * b.w);
    }
    __syncthreads();

    // Load this position's latent vector hv (8 channels, NCHW -> stride 4096)
    const int bb = pos >> 12;
    const int wh = pos & 4095;
    const float* zp = z + ((size_t)bb * ZC + (size_t)l * CDIM) * WHPLANE + wh;
    const float h0 = zp[0 * WHPLANE];
    const float h1 = zp[1 * WHPLANE];
    const float h2 = zp[2 * WHPLANE];
    const float h3 = zp[3 * WHPLANE];
    const float h4 = zp[4 * WHPLANE];
    const float h5 = zp[5 * WHPLANE];
    const float h6 = zp[6 * WHPLANE];
    const float h7 = zp[7 * WHPLANE];
    const float hn2 = S1 * (h0 * h0 + h1 * h1 + h2 * h2 + h3 * h3
                          + h4 * h4 + h5 * h5 + h6 * h6 + h7 * h7);

    // h duplicated into both lanes (once, outside the loop)
    const u64 hd0 = pk2(h0, h0);
    const u64 hd1 = pk2(h1, h1);
    const u64 hd2 = pk2(h2, h2);
    const u64 hd3 = pk2(h3, h3);
    const u64 hd4 = pk2(h4, h4);
    const u64 hd5 = pk2(h5, h5);
    const u64 hd6 = pk2(h6, h6);
    const u64 hd7 = pk2(h7, h7);
    const u64 hn2p = pk2(hn2, hn2);

    // Lane-separated accumulators: lane0 = even codes, lane1 = odd codes
    u64 acc0 = 0ull, acc1 = 0ull, acc2 = 0ull, acc3 = 0ull;
    u64 acc4 = 0ull, acc5 = 0ull, acc6 = 0ull, acc7 = 0ull;
    u64 sume2 = 0ull;
    float mind = 3.4e38f;
    int   mink = 0;

    #pragma unroll 4
    for (int j = 0; j < KCODES / 2; j++) {
        const ulonglong2 q01 = reinterpret_cast<const ulonglong2*>(sct[j])[0];
        const ulonglong2 q23 = reinterpret_cast<const ulonglong2*>(sct[j])[1];
        const ulonglong2 q45 = reinterpret_cast<const ulonglong2*>(sct[j])[2];
        const ulonglong2 q67 = reinterpret_cast<const ulonglong2*>(sct[j])[3];

        // Two independent half-chains (critical path ~20 cyc instead of 36)
        u64 dpA = fadd2(ssn[j], hn2p);
        dpA = ffma2(hd0, q01.x, dpA);
        dpA = ffma2(hd1, q01.y, dpA);
        dpA = ffma2(hd2, q23.x, dpA);
        dpA = ffma2(hd3, q23.y, dpA);

        u64 dpB = fmul2(hd4, q45.x);
        dpB = ffma2(hd5, q45.y, dpB);
        dpB = ffma2(hd6, q67.x, dpB);
        dpB = ffma2(hd7, q67.y, dpB);

        const u64 dp = fadd2(dpA, dpB);

        float d2a, d2b;
        upk2(dp, d2a, d2b);

        // argmin: FMNMX (fma pipe) + compare + select; strict '<' keeps first
        const bool lt0 = d2a < mind;
        mind = fminf(mind, d2a);
        mink = lt0 ? (2 * j) : mink;
        const bool lt1 = d2b < mind;
        mind = fminf(mind, d2b);
        mink = lt1 ? (2 * j + 1) : mink;

        // e = exp(-dist) = 2^(-sqrt(S1*d2)) ; neg folds into MUFU input
        const float e0 = ex2_ap(0.0f - sqrt_ap(fabsf(d2a)));
        const float e1 = ex2_ap(0.0f - sqrt_ap(fabsf(d2b)));
        const u64 ep = pk2(e0, e1);
        sume2 = fadd2(sume2, ep);

        acc0 = ffma2(ep, q01.x, acc0);
        acc1 = ffma2(ep, q01.y, acc1);
        acc2 = ffma2(ep, q23.x, acc2);
        acc3 = ffma2(ep, q23.y, acc3);
        acc4 = ffma2(ep, q45.x, acc4);
        acc5 = ffma2(ep, q45.y, acc5);
        acc6 = ffma2(ep, q67.x, acc6);
        acc7 = ffma2(ep, q67.y, acc7);
    }

    float se0, se1;
    upk2(sume2, se0, se1);
    const float inv = INV_S2n / (se0 + se1);

    float lo, hi, s0, s1, s2, s3, s4, s5, s6, s7;
    upk2(acc0, lo, hi); s0 = (lo + hi) * inv;
    upk2(acc1, lo, hi); s1 = (lo + hi) * inv;
    upk2(acc2, lo, hi); s2 = (lo + hi) * inv;
    upk2(acc3, lo, hi); s3 = (lo + hi) * inv;
    upk2(acc4, lo, hi); s4 = (lo + hi) * inv;
    upk2(acc5, lo, hi); s5 = (lo + hi) * inv;
    upk2(acc6, lo, hi); s6 = (lo + hi) * inv;
    upk2(acc7, lo, hi); s7 = (lo + hi) * inv;

    // soft: (B,W,H,C), c = l*8 + cd -> offset pos*128 + l*8 (32B-aligned)
    {
        float4* sp = reinterpret_cast<float4*>(out_soft + (size_t)pos * ZC + (size_t)l * CDIM);
        sp[0] = make_float4(s0, s1, s2, s3);
        sp[1] = make_float4(s4, s5, s6, s7);
    }
    if (out_hard) {
        // Winning code re-read from global (L2-hot, 32B)
        const float4* cw = reinterpret_cast<const float4*>(codes)
                         + ((size_t)l * KCODES + mink) * 2;
        float4* hp = reinterpret_cast<float4*>(out_hard + (size_t)pos * ZC + (size_t)l * CDIM);
        hp[0] = cw[0];
        hp[1] = cw[1];
    }
    if (out_idx) {
        out_idx[(size_t)pos * LDIM + l] = (float)mink;
    }
}

extern "C" void kernel_launch(void* const* d_in, const int* in_sizes, int n_in,
                              void* d_out, int out_size) {
    const float* z     = (const float*)d_in[0];
    const float* codes = (const float*)d_in[1];
    float* out = (float*)d_out;

    const long long softN = (long long)NPOS * ZC;   // 4,194,304
    const long long idxN  = (long long)NPOS * LDIM; // 524,288

    float* soft = out;
    float* hard = ((long long)out_size >= 2 * softN) ? out + softN : nullptr;
    float* idxo = ((long long)out_size >= 2 * softN + idxN) ? out + 2 * softN : nullptr;

    dim3 grid(NPOS / 256, LDIM);
    sth_kernel<<<grid, 256>>>(z, codes, soft, hard, idxo);
}

// round 7
// speedup vs baseline: 1.0007x; 1.0007x over previous
#include <cuda_runtime.h>
#include <cuda_bf16.h>

// Problem constants
#define ZB 8
#define ZC 128
#define ZW 64
#define ZH 64
#define LDIM 16
#define KCODES 256
#define CDIM 8
#define NPOS (ZB * ZW * ZH)   // 32768 spatial positions
#define WHPLANE (ZW * ZH)     // 4096

typedef unsigned long long u64;

// log2(e)^2 and -2*log2(e)^2 ; 1/S2n to un-scale the soft accumulator
#define S1 2.0813689810056077f
#define S2n (-4.1627379620112154f)
#define INV_S2n (-0.24022650695910071f)

// ---- packed f32x2 helpers (sm_103a) ----
__device__ __forceinline__ u64 pk2(float lo, float hi) {
    u64 r; asm("mov.b64 %0, {%1, %2};" : "=l"(r) : "f"(lo), "f"(hi)); return r;
}
__device__ __forceinline__ void upk2(u64 p, float& lo, float& hi) {
    asm("mov.b64 {%0, %1}, %2;" : "=f"(lo), "=f"(hi) : "l"(p));
}
__device__ __forceinline__ u64 ffma2(u64 a, u64 b, u64 c) {
    u64 d; asm("fma.rn.f32x2 %0, %1, %2, %3;" : "=l"(d) : "l"(a), "l"(b), "l"(c)); return d;
}
__device__ __forceinline__ u64 fmul2(u64 a, u64 b) {
    u64 d; asm("mul.rn.f32x2 %0, %1, %2;" : "=l"(d) : "l"(a), "l"(b)); return d;
}
__device__ __forceinline__ u64 fadd2(u64 a, u64 b) {
    u64 d; asm("add.rn.f32x2 %0, %1, %2;" : "=l"(d) : "l"(a), "l"(b)); return d;
}
__device__ __forceinline__ float sqrt_ap(float x) {
    float r; asm("sqrt.approx.f32 %0, %1;" : "=f"(r) : "f"(x)); return r;
}
__device__ __forceinline__ float ex2_ap(float x) {
    float r; asm("ex2.approx.f32 %0, %1;" : "=f"(r) : "f"(x)); return r;
}

// One block = one latent l (blockIdx.y) x 256 positions (blockIdx.x).
// Each thread owns one (pos, l): loops over K=256 codes in PAIRS.
// f32x2 lanes = (code 2j, code 2j+1) of the same channel. The dot work is
// split into two independent half-chains (shorter critical path), norms are
// pre-packed, argmin uses FMNMX + one select.
__global__ void __launch_bounds__(256, 4)
sth_kernel(const float* __restrict__ z, const float* __restrict__ codes,
           float* __restrict__ out_soft, float* __restrict__ out_hard,
           float* __restrict__ out_idx)
{
    const int l   = blockIdx.y;
    const int tid = threadIdx.x;
    const int pos = blockIdx.x * 256 + tid;

    // Transposed, pre-scaled codebook: sct[j][i] = (S2n*c_{2j}[i], S2n*c_{2j+1}[i])
    __shared__ u64 sct[KCODES / 2][CDIM];  // 8 KB
    __shared__ u64 ssn[KCODES / 2];        // (S1*||c_2j||^2, S1*||c_2j+1||^2) 1 KB

    // Cooperative codebook load: one code per thread (256 threads == 256 codes)
    {
        const float4* cl = reinterpret_cast<const float4*>(codes)
                         + (size_t)l * (KCODES * 2) + 2 * tid;
        const float4 a = cl[0];
        const float4 b = cl[1];
        float* sf = reinterpret_cast<float*>(sct);
        const int j = tid >> 1, lane = tid & 1;
        const int base = j * (CDIM * 2) + lane;
        sf[base +  0] = S2n * a.x;
        sf[base +  2] = S2n * a.y;
        sf[base +  4] = S2n * a.z;
        sf[base +  6] = S2n * a.w;
        sf[base +  8] = S2n * b.x;
        sf[base + 10] = S2n * b.y;
        sf[base + 12] = S2n * b.z;
        sf[base + 14] = S2n * b.w;
        reinterpret_cast<float*>(ssn)[tid] =
            S1 * (a.x * a.x + a.y * a.y + a.z * a.z + a.w * a.w
                + b.x * b.x + b.y * b.y + b.z * b.z + b.w * b.w);
    }
    __syncthreads();

    // Load this position's latent vector hv (8 channels, NCHW -> stride 4096)
    const int bb = pos >> 12;
    const int wh = pos & 4095;
    const float* zp = z + ((size_t)bb * ZC + (size_t)l * CDIM) * WHPLANE + wh;
    const float h0 = zp[0 * WHPLANE];
    const float h1 = zp[1 * WHPLANE];
    const float h2 = zp[2 * WHPLANE];
    const float h3 = zp[3 * WHPLANE];
    const float h4 = zp[4 * WHPLANE];
    const float h5 = zp[5 * WHPLANE];
    const float h6 = zp[6 * WHPLANE];
    const float h7 = zp[7 * WHPLANE];
    const float hn2 = S1 * (h0 * h0 + h1 * h1 + h2 * h2 + h3 * h3
                          + h4 * h4 + h5 * h5 + h6 * h6 + h7 * h7);

    // h duplicated into both lanes (once, outside the loop)
    const u64 hd0 = pk2(h0, h0);
    const u64 hd1 = pk2(h1, h1);
    const u64 hd2 = pk2(h2, h2);
    const u64 hd3 = pk2(h3, h3);
    const u64 hd4 = pk2(h4, h4);
    const u64 hd5 = pk2(h5, h5);
    const u64 hd6 = pk2(h6, h6);
    const u64 hd7 = pk2(h7, h7);
    const u64 hn2p = pk2(hn2, hn2);

    // Lane-separated accumulators: lane0 = even codes, lane1 = odd codes
    u64 acc0 = 0ull, acc1 = 0ull, acc2 = 0ull, acc3 = 0ull;
    u64 acc4 = 0ull, acc5 = 0ull, acc6 = 0ull, acc7 = 0ull;
    u64 sume2 = 0ull;
    float mind = 3.4e38f;
    int   mink = 0;

    #pragma unroll 4
    for (int j = 0; j < KCODES / 2; j++) {
        const ulonglong2 q01 = reinterpret_cast<const ulonglong2*>(sct[j])[0];
        const ulonglong2 q23 = reinterpret_cast<const ulonglong2*>(sct[j])[1];
        const ulonglong2 q45 = reinterpret_cast<const ulonglong2*>(sct[j])[2];
        const ulonglong2 q67 = reinterpret_cast<const ulonglong2*>(sct[j])[3];

        // Two independent half-chains (critical path ~20 cyc instead of 36)
        u64 dpA = fadd2(ssn[j], hn2p);
        dpA = ffma2(hd0, q01.x, dpA);
        dpA = ffma2(hd1, q01.y, dpA);
        dpA = ffma2(hd2, q23.x, dpA);
        dpA = ffma2(hd3, q23.y, dpA);

        u64 dpB = fmul2(hd4, q45.x);
        dpB = ffma2(hd5, q45.y, dpB);
        dpB = ffma2(hd6, q67.x, dpB);
        dpB = ffma2(hd7, q67.y, dpB);

        const u64 dp = fadd2(dpA, dpB);

        float d2a, d2b;
        upk2(dp, d2a, d2b);

        // argmin: FMNMX (fma pipe) + compare + select; strict '<' keeps first
        const bool lt0 = d2a < mind;
        mind = fminf(mind, d2a);
        mink = lt0 ? (2 * j) : mink;
        const bool lt1 = d2b < mind;
        mind = fminf(mind, d2b);
        mink = lt1 ? (2 * j + 1) : mink;

        // e = exp(-dist) = 2^(-sqrt(S1*d2)) ; neg folds into MUFU input
        const float e0 = ex2_ap(0.0f - sqrt_ap(fabsf(d2a)));
        const float e1 = ex2_ap(0.0f - sqrt_ap(fabsf(d2b)));
        const u64 ep = pk2(e0, e1);
        sume2 = fadd2(sume2, ep);

        acc0 = ffma2(ep, q01.x, acc0);
        acc1 = ffma2(ep, q01.y, acc1);
        acc2 = ffma2(ep, q23.x, acc2);
        acc3 = ffma2(ep, q23.y, acc3);
        acc4 = ffma2(ep, q45.x, acc4);
        acc5 = ffma2(ep, q45.y, acc5);
        acc6 = ffma2(ep, q67.x, acc6);
        acc7 = ffma2(ep, q67.y, acc7);
    }

    float se0, se1;
    upk2(sume2, se0, se1);
    const float inv = INV_S2n / (se0 + se1);

    float lo, hi, s0, s1, s2, s3, s4, s5, s6, s7;
    upk2(acc0, lo, hi); s0 = (lo + hi) * inv;
    upk2(acc1, lo, hi); s1 = (lo + hi) * inv;
    upk2(acc2, lo, hi); s2 = (lo + hi) * inv;
    upk2(acc3, lo, hi); s3 = (lo + hi) * inv;
    upk2(acc4, lo, hi); s4 = (lo + hi) * inv;
    upk2(acc5, lo, hi); s5 = (lo + hi) * inv;
    upk2(acc6, lo, hi); s6 = (lo + hi) * inv;
    upk2(acc7, lo, hi); s7 = (lo + hi) * inv;

    // soft: (B,W,H,C), c = l*8 + cd -> offset pos*128 + l*8 (32B-aligned)
    {
        float4* sp = reinterpret_cast<float4*>(out_soft + (size_t)pos * ZC + (size_t)l * CDIM);
        sp[0] = make_float4(s0, s1, s2, s3);
        sp[1] = make_float4(s4, s5, s6, s7);
    }
    if (out_hard) {
        // Winning code re-read from global (L2-hot, 32B)
        const float4* cw = reinterpret_cast<const float4*>(codes)
                         + ((size_t)l * KCODES + mink) * 2;
        float4* hp = reinterpret_cast<float4*>(out_hard + (size_t)pos * ZC + (size_t)l * CDIM);
        hp[0] = cw[0];
        hp[1] = cw[1];
    }
    if (out_idx) {
        out_idx[(size_t)pos * LDIM + l] = (float)mink;
    }
}

extern "C" void kernel_launch(void* const* d_in, const int* in_sizes, int n_in,
                              void* d_out, int out_size) {
    const float* z     = (const float*)d_in[0];
    const float* codes = (const float*)d_in[1];
    float* out = (float*)d_out;

    const long long softN = (long long)NPOS * ZC;   // 4,194,304
    const long long idxN  = (long long)NPOS * LDIM; // 524,288

    float* soft = out;
    float* hard = ((long long)out_size >= 2 * softN) ? out + softN : nullptr;
    float* idxo = ((long long)out_size >= 2 * softN + idxN) ? out + 2 * softN : nullptr;

    dim3 grid(NPOS / 256, LDIM);
    sth_kernel<<<grid, 256>>>(z, codes, soft, hard, idxo);
}